// round 3
// baseline (speedup 1.0000x reference)
#include <cuda_runtime.h>
#include <cuda_bf16.h>
#include <stdint.h>

#define NMAX 50000
#define HD 128
#define NGRAPH 512

// ---------------- scratch (static device globals; no allocation) ----------------
// float4 typed => guaranteed 16-byte alignment for vector ld/st and red.v4
__device__ float  g_deg[NMAX];
__device__ float  g_dinv[NMAX];
__device__ float4 g_ts[(size_t)NMAX * HD / 4];   // (h @ W) * dinv[row]
__device__ float4 g_agg[(size_t)NMAX * HD / 4];  // init = ts (self loop), += ts[src] per edge
__device__ float4 g_h[(size_t)NMAX * HD / 4];    // layer output
__device__ float  g_cnt[NGRAPH];

// ---------------- degree / dinv ----------------
__global__ void k_deg_init(int N) {
    int i = blockIdx.x * blockDim.x + threadIdx.x;
    if (i < N) g_deg[i] = 1.0f;  // self loop
}

// edge_index is int32 on device (JAX silently downcasts int64 without x64 mode)
__global__ void k_deg_count(const int* __restrict__ ei, int E) {
    int e = blockIdx.x * blockDim.x + threadIdx.x;
    if (e < E) {
        int d = ei[(size_t)E + e];
        atomicAdd(&g_deg[d], 1.0f);
    }
}

__global__ void k_dinv(int N) {
    int i = blockIdx.x * blockDim.x + threadIdx.x;
    if (i < N) g_dinv[i] = rsqrtf(g_deg[i]);
}

// ---------------- SGEMM (N x 128) @ (128 x 128), epilogue: *dinv[row], dual-write ----------------
// 128x128 output tile per block, K chunks of 16, 256 threads, 8x8 per thread.
__global__ __launch_bounds__(256) void k_sgemm_scale(
    const float* __restrict__ A, const float* __restrict__ W, int N)
{
    __shared__ float As[16][132];  // [k][row]
    __shared__ float Bs[16][132];  // [k][col]

    const int tid  = threadIdx.x;
    const int row0 = blockIdx.x * 128;
    const int tx = tid & 15;   // col group
    const int ty = tid >> 4;   // row group

    float acc[8][8];
#pragma unroll
    for (int i = 0; i < 8; i++)
#pragma unroll
        for (int j = 0; j < 8; j++) acc[i][j] = 0.0f;

    for (int k0 = 0; k0 < 128; k0 += 16) {
        // A tile: 128 rows x 16 cols, 512 float4 loads, 2 per thread
#pragma unroll
        for (int j = 0; j < 2; j++) {
            int f = tid + j * 256;
            int r = f >> 2, c4 = f & 3;
            float4 v = make_float4(0.f, 0.f, 0.f, 0.f);
            if (row0 + r < N)
                v = *(const float4*)&A[(size_t)(row0 + r) * 128 + k0 + c4 * 4];
            As[c4 * 4 + 0][r] = v.x;
            As[c4 * 4 + 1][r] = v.y;
            As[c4 * 4 + 2][r] = v.z;
            As[c4 * 4 + 3][r] = v.w;
        }
        // B tile: 16 rows x 128 cols
#pragma unroll
        for (int j = 0; j < 2; j++) {
            int f = tid + j * 256;
            int r = f >> 5, c4 = f & 31;
            float4 v = *(const float4*)&W[(size_t)(k0 + r) * 128 + c4 * 4];
            *(float4*)&Bs[r][c4 * 4] = v;
        }
        __syncthreads();

#pragma unroll
        for (int k = 0; k < 16; k++) {
            float a[8], b[8];
#pragma unroll
            for (int i = 0; i < 8; i++) a[i] = As[k][ty * 8 + i];
#pragma unroll
            for (int i = 0; i < 8; i++) b[i] = Bs[k][tx * 8 + i];
#pragma unroll
            for (int i = 0; i < 8; i++)
#pragma unroll
                for (int j = 0; j < 8; j++) acc[i][j] = fmaf(a[i], b[j], acc[i][j]);
        }
        __syncthreads();
    }

    // epilogue: ts = acc * dinv[row]; write to g_ts and g_agg (agg init covers self loop)
#pragma unroll
    for (int i = 0; i < 8; i++) {
        int r = row0 + ty * 8 + i;
        if (r < N) {
            float s = g_dinv[r];
#pragma unroll
            for (int j = 0; j < 8; j += 4) {
                float4 v = make_float4(acc[i][j] * s, acc[i][j + 1] * s,
                                       acc[i][j + 2] * s, acc[i][j + 3] * s);
                size_t off4 = ((size_t)r * 128 + tx * 8 + j) >> 2;
                g_ts[off4]  = v;
                g_agg[off4] = v;
            }
        }
    }
}

// ---------------- edge scatter: one warp per edge, red.global.add.v4 ----------------
__global__ __launch_bounds__(256) void k_scatter(const int* __restrict__ ei, int E) {
    int w = (int)((blockIdx.x * (unsigned)blockDim.x + threadIdx.x) >> 5);
    int lane = threadIdx.x & 31;
    if (w >= E) return;
    int src = ei[w];
    int dst = ei[(size_t)E + w];
    float4 v = g_ts[(size_t)src * 32 + lane];
    float4* d = &g_agg[(size_t)dst * 32 + lane];
    asm volatile("red.global.add.v4.f32 [%0], {%1, %2, %3, %4};"
                 :: "l"(d), "f"(v.x), "f"(v.y), "f"(v.z), "f"(v.w) : "memory");
}

// ---------------- finalize: h = relu(dinv[row]*agg + b) ----------------
__global__ __launch_bounds__(256) void k_finalize(const float* __restrict__ bias, int N) {
    int idx = blockIdx.x * blockDim.x + threadIdx.x;
    int node = idx >> 5, lane = idx & 31;
    if (node >= N) return;
    float s = g_dinv[node];
    float4 a = g_agg[(size_t)node * 32 + lane];
    float4 b = make_float4(bias[lane * 4 + 0], bias[lane * 4 + 1],
                           bias[lane * 4 + 2], bias[lane * 4 + 3]);
    float4 o;
    o.x = fmaxf(fmaf(s, a.x, b.x), 0.f);
    o.y = fmaxf(fmaf(s, a.y, b.y), 0.f);
    o.z = fmaxf(fmaf(s, a.z, b.z), 0.f);
    o.w = fmaxf(fmaf(s, a.w, b.w), 0.f);
    g_h[(size_t)node * 32 + lane] = o;
}

// ---------------- pooling ----------------
__global__ void k_zero_out(float* out, int n) {
    int i = blockIdx.x * blockDim.x + threadIdx.x;
    if (i < n) out[i] = 0.0f;
    if (i < NGRAPH) g_cnt[i] = 0.0f;
}

__global__ __launch_bounds__(256) void k_pool(const int* __restrict__ batch,
                                              float* __restrict__ out, int N) {
    int idx = blockIdx.x * blockDim.x + threadIdx.x;
    int node = idx >> 5, lane = idx & 31;
    if (node >= N) return;
    int g = batch[node];
    float4 v = g_h[(size_t)node * 32 + lane];
    float* d = out + (size_t)g * 128 + lane * 4;
    asm volatile("red.global.add.v4.f32 [%0], {%1, %2, %3, %4};"
                 :: "l"(d), "f"(v.x), "f"(v.y), "f"(v.z), "f"(v.w) : "memory");
    if (lane == 0) atomicAdd(&g_cnt[g], 1.0f);
}

__global__ void k_pool_fin(float* out, int n) {
    int i = blockIdx.x * blockDim.x + threadIdx.x;
    if (i < n) {
        int g = i >> 7;
        out[i] = out[i] / fmaxf(g_cnt[g], 1.0f);
    }
}

// ---------------- launch ----------------
extern "C" void kernel_launch(void* const* d_in, const int* in_sizes, int n_in,
                              void* d_out, int out_size) {
    const float* x     = (const float*)d_in[0];
    // d_in[1] = edge_attr (unused by GCNConv)
    const float* W1    = (const float*)d_in[2];
    const float* b1    = (const float*)d_in[3];
    const float* W2    = (const float*)d_in[4];
    const float* b2    = (const float*)d_in[5];
    const float* W3    = (const float*)d_in[6];
    const float* b3    = (const float*)d_in[7];
    const int*   ei    = (const int*)d_in[8];     // int32 (JAX x64 disabled)
    const int*   batch = (const int*)d_in[9];     // int32
    float* out = (float*)d_out;

    const int N = in_sizes[0] / HD;
    const int E = in_sizes[8] / 2;

    void* p_h = nullptr;
    cudaGetSymbolAddress(&p_h, g_h);
    const float* hbuf = (const float*)p_h;

    const int T = 256;
    // degree + dinv
    k_deg_init<<<(N + T - 1) / T, T>>>(N);
    k_deg_count<<<(E + T - 1) / T, T>>>(ei, E);
    k_dinv<<<(N + T - 1) / T, T>>>(N);

    const int gemm_blocks = (N + 127) / 128;
    const int node_warp_blocks = (N * 32 + T - 1) / T;
    const int edge_warp_blocks = (int)(((long long)E * 32 + T - 1) / T);

    // layer 1
    k_sgemm_scale<<<gemm_blocks, T>>>(x, W1, N);
    k_scatter<<<edge_warp_blocks, T>>>(ei, E);
    k_finalize<<<node_warp_blocks, T>>>(b1, N);
    // layer 2
    k_sgemm_scale<<<gemm_blocks, T>>>(hbuf, W2, N);
    k_scatter<<<edge_warp_blocks, T>>>(ei, E);
    k_finalize<<<node_warp_blocks, T>>>(b2, N);
    // layer 3
    k_sgemm_scale<<<gemm_blocks, T>>>(hbuf, W3, N);
    k_scatter<<<edge_warp_blocks, T>>>(ei, E);
    k_finalize<<<node_warp_blocks, T>>>(b3, N);

    // mean pool
    k_zero_out<<<(out_size + T - 1) / T, T>>>(out, out_size);
    k_pool<<<node_warp_blocks, T>>>(batch, out, N);
    k_pool_fin<<<(out_size + T - 1) / T, T>>>(out, out_size);
}

// round 4
// speedup vs baseline: 1.5248x; 1.5248x over previous
#include <cuda_runtime.h>
#include <cuda_bf16.h>
#include <stdint.h>

#define NMAX 50000
#define EMAX 1000000
#define HD 128
#define NGRAPH 512

// ---------------- scratch (static device globals; no allocation) ----------------
__device__ float  g_dinv[NMAX];
__device__ int    g_hist[NMAX];        // in-degree (excl self loop)
__device__ int    g_rowptr[NMAX + 1];
__device__ int    g_cursor[NMAX];
__device__ int    g_csr[EMAX];         // src node id per dst-sorted edge
__device__ float4 g_ts[(size_t)NMAX * HD / 4];   // (h @ W) * dinv[row]
__device__ float4 g_h[(size_t)NMAX * HD / 4];    // layer output
__device__ float  g_cnt[NGRAPH];

// ---------------- CSR build ----------------
__global__ void k_zero_meta(int N) {
    int i = blockIdx.x * blockDim.x + threadIdx.x;
    if (i < N) g_hist[i] = 0;
    if (i < NGRAPH) g_cnt[i] = 0.0f;
}

__global__ void k_hist(const int* __restrict__ ei, int E) {
    int e = blockIdx.x * blockDim.x + threadIdx.x;
    if (e < E) atomicAdd(&g_hist[ei[(size_t)E + e]], 1);
}

__global__ void k_graph_cnt(const int* __restrict__ batch, int N) {
    int i = blockIdx.x * blockDim.x + threadIdx.x;
    if (i < N) atomicAdd(&g_cnt[batch[i]], 1.0f);
}

// single-block exclusive scan over g_hist -> g_rowptr / g_cursor
__global__ __launch_bounds__(1024) void k_scan(int N) {
    __shared__ int wsum[32];
    __shared__ int carry;
    const int tid = threadIdx.x, lane = tid & 31, wid = tid >> 5;
    if (tid == 0) { carry = 0; g_rowptr[0] = 0; }
    __syncthreads();
    for (int base = 0; base < N; base += 1024) {
        int i = base + tid;
        int v = (i < N) ? g_hist[i] : 0;
        int x = v;
#pragma unroll
        for (int o = 1; o < 32; o <<= 1) {
            int y = __shfl_up_sync(0xffffffffu, x, o);
            if (lane >= o) x += y;
        }
        if (lane == 31) wsum[wid] = x;
        __syncthreads();
        if (wid == 0) {
            int s = wsum[lane];
#pragma unroll
            for (int o = 1; o < 32; o <<= 1) {
                int y = __shfl_up_sync(0xffffffffu, s, o);
                if (lane >= o) s += y;
            }
            wsum[lane] = s;
        }
        __syncthreads();
        int incl = x + (wid > 0 ? wsum[wid - 1] : 0) + carry;
        if (i < N) {
            g_rowptr[i + 1] = incl;
            g_cursor[i] = incl - v;
        }
        __syncthreads();
        if (tid == 0) carry += wsum[31];
        __syncthreads();
    }
}

__global__ void k_dinv(int N) {
    int i = blockIdx.x * blockDim.x + threadIdx.x;
    if (i < N) g_dinv[i] = rsqrtf((float)g_hist[i] + 1.0f);
}

__global__ void k_fill(const int* __restrict__ ei, int E) {
    int e = blockIdx.x * blockDim.x + threadIdx.x;
    if (e < E) {
        int src = ei[e];
        int dst = ei[(size_t)E + e];
        int pos = atomicAdd(&g_cursor[dst], 1);
        g_csr[pos] = src;
    }
}

// ---------------- SGEMM (N x 128) @ (128 x 128), epilogue: *dinv[row] -> g_ts ----------------
__global__ __launch_bounds__(256) void k_sgemm_scale(
    const float* __restrict__ A, const float* __restrict__ W, int N)
{
    __shared__ float As[16][132];
    __shared__ float Bs[16][132];

    const int tid  = threadIdx.x;
    const int row0 = blockIdx.x * 128;
    const int tx = tid & 15;
    const int ty = tid >> 4;

    float acc[8][8];
#pragma unroll
    for (int i = 0; i < 8; i++)
#pragma unroll
        for (int j = 0; j < 8; j++) acc[i][j] = 0.0f;

    for (int k0 = 0; k0 < 128; k0 += 16) {
#pragma unroll
        for (int j = 0; j < 2; j++) {
            int f = tid + j * 256;
            int r = f >> 2, c4 = f & 3;
            float4 v = make_float4(0.f, 0.f, 0.f, 0.f);
            if (row0 + r < N)
                v = *(const float4*)&A[(size_t)(row0 + r) * 128 + k0 + c4 * 4];
            As[c4 * 4 + 0][r] = v.x;
            As[c4 * 4 + 1][r] = v.y;
            As[c4 * 4 + 2][r] = v.z;
            As[c4 * 4 + 3][r] = v.w;
        }
#pragma unroll
        for (int j = 0; j < 2; j++) {
            int f = tid + j * 256;
            int r = f >> 5, c4 = f & 31;
            float4 v = *(const float4*)&W[(size_t)(k0 + r) * 128 + c4 * 4];
            *(float4*)&Bs[r][c4 * 4] = v;
        }
        __syncthreads();

#pragma unroll
        for (int k = 0; k < 16; k++) {
            float a[8], b[8];
#pragma unroll
            for (int i = 0; i < 8; i++) a[i] = As[k][ty * 8 + i];
#pragma unroll
            for (int i = 0; i < 8; i++) b[i] = Bs[k][tx * 8 + i];
#pragma unroll
            for (int i = 0; i < 8; i++)
#pragma unroll
                for (int j = 0; j < 8; j++) acc[i][j] = fmaf(a[i], b[j], acc[i][j]);
        }
        __syncthreads();
    }

#pragma unroll
    for (int i = 0; i < 8; i++) {
        int r = row0 + ty * 8 + i;
        if (r < N) {
            float s = g_dinv[r];
#pragma unroll
            for (int j = 0; j < 8; j += 4) {
                float4 v = make_float4(acc[i][j] * s, acc[i][j + 1] * s,
                                       acc[i][j + 2] * s, acc[i][j + 3] * s);
                g_ts[((size_t)r * 128 + tx * 8 + j) >> 2] = v;
            }
        }
    }
}

// ---------------- gather-aggregate + fused finalize (and optional fused pool) ----------------
// one warp per dst node; lane = one float4 chunk of the 128-dim row
template <bool POOL>
__global__ __launch_bounds__(256) void k_gather(const float* __restrict__ bias,
                                                const int* __restrict__ batch,
                                                float* __restrict__ out, int N)
{
    int idx  = blockIdx.x * blockDim.x + threadIdx.x;
    int node = idx >> 5, lane = idx & 31;
    if (node >= N) return;

    // self loop
    float4 acc = g_ts[(size_t)node * 32 + lane];

    int p   = g_rowptr[node];
    int end = g_rowptr[node + 1];

    for (; p + 4 <= end; p += 4) {
        int s0 = g_csr[p], s1 = g_csr[p + 1], s2 = g_csr[p + 2], s3 = g_csr[p + 3];
        float4 v0 = g_ts[(size_t)s0 * 32 + lane];
        float4 v1 = g_ts[(size_t)s1 * 32 + lane];
        float4 v2 = g_ts[(size_t)s2 * 32 + lane];
        float4 v3 = g_ts[(size_t)s3 * 32 + lane];
        acc.x += v0.x + v1.x + v2.x + v3.x;
        acc.y += v0.y + v1.y + v2.y + v3.y;
        acc.z += v0.z + v1.z + v2.z + v3.z;
        acc.w += v0.w + v1.w + v2.w + v3.w;
    }
    for (; p < end; p++) {
        int s = g_csr[p];
        float4 v = g_ts[(size_t)s * 32 + lane];
        acc.x += v.x; acc.y += v.y; acc.z += v.z; acc.w += v.w;
    }

    float s = g_dinv[node];
    float4 b = *((const float4*)bias + lane);
    float4 o;
    o.x = fmaxf(fmaf(s, acc.x, b.x), 0.f);
    o.y = fmaxf(fmaf(s, acc.y, b.y), 0.f);
    o.z = fmaxf(fmaf(s, acc.z, b.z), 0.f);
    o.w = fmaxf(fmaf(s, acc.w, b.w), 0.f);

    if (POOL) {
        int g = batch[node];
        float* d = out + (size_t)g * 128 + lane * 4;
        asm volatile("red.global.add.v4.f32 [%0], {%1, %2, %3, %4};"
                     :: "l"(d), "f"(o.x), "f"(o.y), "f"(o.z), "f"(o.w) : "memory");
    } else {
        g_h[(size_t)node * 32 + lane] = o;
    }
}

// ---------------- pooling tail ----------------
__global__ void k_zero_out(float* out, int n) {
    int i = blockIdx.x * blockDim.x + threadIdx.x;
    if (i < n) out[i] = 0.0f;
}

__global__ void k_pool_fin(float* out, int n) {
    int i = blockIdx.x * blockDim.x + threadIdx.x;
    if (i < n) {
        int g = i >> 7;
        out[i] = out[i] / fmaxf(g_cnt[g], 1.0f);
    }
}

// ---------------- launch ----------------
extern "C" void kernel_launch(void* const* d_in, const int* in_sizes, int n_in,
                              void* d_out, int out_size) {
    const float* x     = (const float*)d_in[0];
    // d_in[1] = edge_attr (unused by GCNConv)
    const float* W1    = (const float*)d_in[2];
    const float* b1    = (const float*)d_in[3];
    const float* W2    = (const float*)d_in[4];
    const float* b2    = (const float*)d_in[5];
    const float* W3    = (const float*)d_in[6];
    const float* b3    = (const float*)d_in[7];
    const int*   ei    = (const int*)d_in[8];     // int32 (JAX x64 disabled)
    const int*   batch = (const int*)d_in[9];     // int32
    float* out = (float*)d_out;

    const int N = in_sizes[0] / HD;
    const int E = in_sizes[8] / 2;

    void* p_h = nullptr;
    cudaGetSymbolAddress(&p_h, g_h);
    const float* hbuf = (const float*)p_h;

    const int T = 256;
    const int nb_N = (N + T - 1) / T;
    const int nb_E = (E + T - 1) / T;
    const int gemm_blocks = (N + 127) / 128;
    const int node_warp_blocks = (N * 32 + T - 1) / T;

    // CSR build + normalization (once, reused by all 3 layers)
    k_zero_meta<<<nb_N, T>>>(N);
    k_hist<<<nb_E, T>>>(ei, E);
    k_graph_cnt<<<nb_N, T>>>(batch, N);
    k_scan<<<1, 1024>>>(N);
    k_dinv<<<nb_N, T>>>(N);
    k_fill<<<nb_E, T>>>(ei, E);
    k_zero_out<<<(out_size + T - 1) / T, T>>>(out, out_size);

    // layer 1
    k_sgemm_scale<<<gemm_blocks, T>>>(x, W1, N);
    k_gather<false><<<node_warp_blocks, T>>>(b1, batch, out, N);
    // layer 2
    k_sgemm_scale<<<gemm_blocks, T>>>(hbuf, W2, N);
    k_gather<false><<<node_warp_blocks, T>>>(b2, batch, out, N);
    // layer 3 (fused mean-pool accumulation)
    k_sgemm_scale<<<gemm_blocks, T>>>(hbuf, W3, N);
    k_gather<true><<<node_warp_blocks, T>>>(b3, batch, out, N);

    k_pool_fin<<<(out_size + T - 1) / T, T>>>(out, out_size);
}

// round 6
// speedup vs baseline: 1.8920x; 1.2408x over previous
#include <cuda_runtime.h>
#include <cuda_bf16.h>
#include <stdint.h>

#define NMAX 50000
#define EMAX 1000000
#define HD 128
#define NGRAPH 512
#define SCAN_B 1024
#define MAXBLK 64

// ---------------- scratch (static device globals; no allocation) ----------------
__device__ float  g_dinv[NMAX];
__device__ int    g_hist[NMAX];        // in-degree (excl self loop)
__device__ int    g_rowptr[NMAX + 1];
__device__ int    g_cursor[NMAX];
__device__ int    g_bsum[MAXBLK];
__device__ int    g_csr[EMAX];         // src node id per dst-sorted edge
__device__ float4 g_ts[(size_t)NMAX * HD / 4];   // (h @ W) * dinv[row]
__device__ float4 g_h[(size_t)NMAX * HD / 4];    // layer output
__device__ float  g_cnt[NGRAPH];

__device__ __forceinline__ uint32_t smem_u32(const void* p) {
    return (uint32_t)__cvta_generic_to_shared(p);
}

// ---------------- CSR build ----------------
__global__ void k_zero_meta(int N) {
    int i = blockIdx.x * blockDim.x + threadIdx.x;
    if (i < N) g_hist[i] = 0;
    if (i < NGRAPH) g_cnt[i] = 0.0f;
}

__global__ void k_hist(const int* __restrict__ ei, int E) {
    int e = blockIdx.x * blockDim.x + threadIdx.x;
    if (e < E) atomicAdd(&g_hist[ei[(size_t)E + e]], 1);
}

// stage 1: per-block inclusive scan; block totals to g_bsum
__global__ __launch_bounds__(SCAN_B) void k_scan1(int N) {
    __shared__ int wsum[32];
    const int tid = threadIdx.x, lane = tid & 31, wid = tid >> 5;
    int i = blockIdx.x * SCAN_B + tid;
    int v = (i < N) ? g_hist[i] : 0;
    int x = v;
#pragma unroll
    for (int o = 1; o < 32; o <<= 1) {
        int y = __shfl_up_sync(0xffffffffu, x, o);
        if (lane >= o) x += y;
    }
    if (lane == 31) wsum[wid] = x;
    __syncthreads();
    if (wid == 0) {
        int s = wsum[lane];
#pragma unroll
        for (int o = 1; o < 32; o <<= 1) {
            int y = __shfl_up_sync(0xffffffffu, s, o);
            if (lane >= o) s += y;
        }
        wsum[lane] = s;
    }
    __syncthreads();
    int incl = x + (wid > 0 ? wsum[wid - 1] : 0);
    if (i < N) g_rowptr[i + 1] = incl;          // pre-offset
    if (tid == SCAN_B - 1) g_bsum[blockIdx.x] = incl;
}

// stage 2: one warp exclusive-scans the block sums in place
__global__ void k_scan2(int nb) {
    int lane = threadIdx.x;
    int carry = 0;
    for (int base = 0; base < nb; base += 32) {
        int v = (base + lane < nb) ? g_bsum[base + lane] : 0;
        int x = v;
#pragma unroll
        for (int o = 1; o < 32; o <<= 1) {
            int y = __shfl_up_sync(0xffffffffu, x, o);
            if (lane >= o) x += y;
        }
        if (base + lane < nb) g_bsum[base + lane] = x - v + carry;  // exclusive
        carry += __shfl_sync(0xffffffffu, x, 31);
    }
}

// stage 3: apply offsets; also dinv, cursor, per-graph counts
__global__ __launch_bounds__(SCAN_B) void k_scan3(const int* __restrict__ batch, int N) {
    int i = blockIdx.x * SCAN_B + threadIdx.x;
    if (i >= N) return;
    int rp = g_rowptr[i + 1] + g_bsum[blockIdx.x];
    g_rowptr[i + 1] = rp;
    int h = g_hist[i];
    g_cursor[i] = rp - h;
    g_dinv[i] = rsqrtf((float)h + 1.0f);
    atomicAdd(&g_cnt[batch[i]], 1.0f);
    if (i == 0) g_rowptr[0] = 0;
}

__global__ void k_fill(const int* __restrict__ ei, int E) {
    int e = blockIdx.x * blockDim.x + threadIdx.x;
    if (e < E) {
        int src = ei[e];
        int dst = ei[(size_t)E + e];
        int pos = atomicAdd(&g_cursor[dst], 1);
        g_csr[pos] = src;
    }
}

// ---------------- SGEMM (N x 128) @ (128 x 128), double-buffered, epilogue *dinv ----------------
// 128x128 tile, 256 threads, 8x8/thread. B via cp.async, A via LDG->reg->STS (transposed).
__global__ __launch_bounds__(256, 2) void k_sgemm_scale(
    const float* __restrict__ A, const float* __restrict__ W, int N)
{
    __shared__ float As[2][16][132];   // [buf][k][row]
    __shared__ float Bs[2][16][132];   // [buf][k][col]

    const int tid  = threadIdx.x;
    const int row0 = blockIdx.x * 128;
    const int tx = tid & 15;
    const int ty = tid >> 4;

    float acc[8][8];
#pragma unroll
    for (int i = 0; i < 8; i++)
#pragma unroll
        for (int j = 0; j < 8; j++) acc[i][j] = 0.0f;

    float4 pa[2];

    auto ldgA = [&](int k0) {
#pragma unroll
        for (int j = 0; j < 2; j++) {
            int f = tid + j * 256;
            int r = f >> 2, c4 = f & 3;
            pa[j] = make_float4(0.f, 0.f, 0.f, 0.f);
            if (row0 + r < N)
                pa[j] = *(const float4*)&A[(size_t)(row0 + r) * 128 + k0 * 16 + c4 * 4];
        }
    };
    auto stsA = [&](int buf) {
#pragma unroll
        for (int j = 0; j < 2; j++) {
            int f = tid + j * 256;
            int r = f >> 2, c4 = f & 3;
            As[buf][c4 * 4 + 0][r] = pa[j].x;
            As[buf][c4 * 4 + 1][r] = pa[j].y;
            As[buf][c4 * 4 + 2][r] = pa[j].z;
            As[buf][c4 * 4 + 3][r] = pa[j].w;
        }
    };
    // full 16x128 B tile: 512 float4 transfers, 2 per thread
    auto issueB = [&](int k0, int buf) {
#pragma unroll
        for (int j = 0; j < 2; j++) {
            int f = tid + j * 256;
            int r = f >> 5, c4 = f & 31;
            const float* src = &W[(size_t)(k0 * 16 + r) * 128 + c4 * 4];
            uint32_t dst = smem_u32(&Bs[buf][r][c4 * 4]);
            asm volatile("cp.async.cg.shared.global [%0], [%1], 16;\n"
                         :: "r"(dst), "l"(src));
        }
    };

    // prologue: chunk 0
    ldgA(0);
    issueB(0, 0);
    asm volatile("cp.async.commit_group;\n");
    stsA(0);

    for (int k0 = 0; k0 < 8; k0++) {
        const int buf = k0 & 1;
        asm volatile("cp.async.wait_group 0;\n");
        __syncthreads();                       // chunk k0 (A sts + B async) visible

        if (k0 < 7) issueB(k0 + 1, buf ^ 1);
        asm volatile("cp.async.commit_group;\n");
        if (k0 < 7) ldgA(k0 + 1);

#pragma unroll
        for (int k = 0; k < 16; k++) {
            float4 a0 = *(const float4*)&As[buf][k][ty * 8];
            float4 a1 = *(const float4*)&As[buf][k][ty * 8 + 4];
            float4 b0 = *(const float4*)&Bs[buf][k][tx * 8];
            float4 b1 = *(const float4*)&Bs[buf][k][tx * 8 + 4];
            float a[8] = {a0.x, a0.y, a0.z, a0.w, a1.x, a1.y, a1.z, a1.w};
            float b[8] = {b0.x, b0.y, b0.z, b0.w, b1.x, b1.y, b1.z, b1.w};
#pragma unroll
            for (int i = 0; i < 8; i++)
#pragma unroll
                for (int j = 0; j < 8; j++) acc[i][j] = fmaf(a[i], b[j], acc[i][j]);
        }

        if (k0 < 7) stsA(buf ^ 1);
    }

    // epilogue: ts = acc * dinv[row]
#pragma unroll
    for (int i = 0; i < 8; i++) {
        int r = row0 + ty * 8 + i;
        if (r < N) {
            float s = g_dinv[r];
#pragma unroll
            for (int j = 0; j < 8; j += 4) {
                float4 v = make_float4(acc[i][j] * s, acc[i][j + 1] * s,
                                       acc[i][j + 2] * s, acc[i][j + 3] * s);
                g_ts[((size_t)r * 128 + tx * 8 + j) >> 2] = v;
            }
        }
    }
}

// ---------------- gather-aggregate + fused finalize (and optional fused pool) ----------------
template <bool POOL>
__global__ __launch_bounds__(256) void k_gather(const float* __restrict__ bias,
                                                const int* __restrict__ batch,
                                                float* __restrict__ out, int N)
{
    int idx  = blockIdx.x * blockDim.x + threadIdx.x;
    int node = idx >> 5, lane = idx & 31;
    if (node >= N) return;

    float4 acc = g_ts[(size_t)node * 32 + lane];   // self loop

    int p   = g_rowptr[node];
    int end = g_rowptr[node + 1];

    for (; p + 4 <= end; p += 4) {
        int s0 = g_csr[p], s1 = g_csr[p + 1], s2 = g_csr[p + 2], s3 = g_csr[p + 3];
        float4 v0 = g_ts[(size_t)s0 * 32 + lane];
        float4 v1 = g_ts[(size_t)s1 * 32 + lane];
        float4 v2 = g_ts[(size_t)s2 * 32 + lane];
        float4 v3 = g_ts[(size_t)s3 * 32 + lane];
        acc.x += v0.x + v1.x + v2.x + v3.x;
        acc.y += v0.y + v1.y + v2.y + v3.y;
        acc.z += v0.z + v1.z + v2.z + v3.z;
        acc.w += v0.w + v1.w + v2.w + v3.w;
    }
    for (; p < end; p++) {
        int s = g_csr[p];
        float4 v = g_ts[(size_t)s * 32 + lane];
        acc.x += v.x; acc.y += v.y; acc.z += v.z; acc.w += v.w;
    }

    float s = g_dinv[node];
    float4 b = *((const float4*)bias + lane);
    float4 o;
    o.x = fmaxf(fmaf(s, acc.x, b.x), 0.f);
    o.y = fmaxf(fmaf(s, acc.y, b.y), 0.f);
    o.z = fmaxf(fmaf(s, acc.z, b.z), 0.f);
    o.w = fmaxf(fmaf(s, acc.w, b.w), 0.f);

    if (POOL) {
        int g = batch[node];
        float* d = out + (size_t)g * 128 + lane * 4;
        asm volatile("red.global.add.v4.f32 [%0], {%1, %2, %3, %4};"
                     :: "l"(d), "f"(o.x), "f"(o.y), "f"(o.z), "f"(o.w) : "memory");
    } else {
        g_h[(size_t)node * 32 + lane] = o;
    }
}

// ---------------- pooling tail ----------------
__global__ void k_zero_out(float* out, int n) {
    int i = blockIdx.x * blockDim.x + threadIdx.x;
    if (i < n) out[i] = 0.0f;
}

__global__ void k_pool_fin(float* out, int n) {
    int i = blockIdx.x * blockDim.x + threadIdx.x;
    if (i < n) {
        int g = i >> 7;
        out[i] = out[i] / fmaxf(g_cnt[g], 1.0f);
    }
}

// ---------------- launch ----------------
extern "C" void kernel_launch(void* const* d_in, const int* in_sizes, int n_in,
                              void* d_out, int out_size) {
    const float* x     = (const float*)d_in[0];
    // d_in[1] = edge_attr (unused by GCNConv)
    const float* W1    = (const float*)d_in[2];
    const float* b1    = (const float*)d_in[3];
    const float* W2    = (const float*)d_in[4];
    const float* b2    = (const float*)d_in[5];
    const float* W3    = (const float*)d_in[6];
    const float* b3    = (const float*)d_in[7];
    const int*   ei    = (const int*)d_in[8];     // int32 (JAX x64 disabled)
    const int*   batch = (const int*)d_in[9];     // int32
    float* out = (float*)d_out;

    const int N = in_sizes[0] / HD;
    const int E = in_sizes[8] / 2;

    void* p_h = nullptr;
    cudaGetSymbolAddress(&p_h, g_h);
    const float* hbuf = (const float*)p_h;

    const int T = 256;
    const int nb_N = (N + T - 1) / T;
    const int nb_E = (E + T - 1) / T;
    const int gemm_blocks = (N + 127) / 128;
    const int node_warp_blocks = (N * 32 + T - 1) / T;
    const int scan_blocks = (N + SCAN_B - 1) / SCAN_B;

    // CSR build + normalization (once, reused by all 3 layers)
    k_zero_meta<<<nb_N, T>>>(N);
    k_hist<<<nb_E, T>>>(ei, E);
    k_scan1<<<scan_blocks, SCAN_B>>>(N);
    k_scan2<<<1, 32>>>(scan_blocks);
    k_scan3<<<scan_blocks, SCAN_B>>>(batch, N);
    k_fill<<<nb_E, T>>>(ei, E);
    k_zero_out<<<(out_size + T - 1) / T, T>>>(out, out_size);

    // layer 1
    k_sgemm_scale<<<gemm_blocks, T>>>(x, W1, N);
    k_gather<false><<<node_warp_blocks, T>>>(b1, batch, out, N);
    // layer 2
    k_sgemm_scale<<<gemm_blocks, T>>>(hbuf, W2, N);
    k_gather<false><<<node_warp_blocks, T>>>(b2, batch, out, N);
    // layer 3 (fused mean-pool accumulation)
    k_sgemm_scale<<<gemm_blocks, T>>>(hbuf, W3, N);
    k_gather<true><<<node_warp_blocks, T>>>(b3, batch, out, N);

    k_pool_fin<<<(out_size + T - 1) / T, T>>>(out, out_size);
}

// round 7
// speedup vs baseline: 1.9719x; 1.0423x over previous
#include <cuda_runtime.h>
#include <cuda_bf16.h>
#include <stdint.h>

#define NMAX 50000
#define EMAX 1000000
#define HD 128
#define NGRAPH 512
#define SCAN_B 1024
#define MAXBLK 64
#define ASTRIDE 36
#define WSTRIDE 132

// ---------------- scratch (static device globals; no allocation) ----------------
__device__ float  g_dinv[NMAX];
__device__ int    g_hist[NMAX];
__device__ int    g_rowptr[NMAX + 1];
__device__ int    g_cursor[NMAX];
__device__ int    g_bsum[MAXBLK];
__device__ int    g_csr[EMAX];
__device__ float4 g_ts[(size_t)NMAX * HD / 4];   // (h @ W) * dinv[row]
__device__ float4 g_h[(size_t)NMAX * HD / 4];    // layer output
__device__ float  g_cnt[NGRAPH];
__device__ float  g_Wb[3][HD * HD];              // tf32-big part of weights
__device__ float  g_Ws[3][HD * HD];              // residual part

__device__ __forceinline__ uint32_t smem_u32(const void* p) {
    return (uint32_t)__cvta_generic_to_shared(p);
}

// ---------------- CSR build ----------------
__global__ void k_zero_meta(int N) {
    int i = blockIdx.x * blockDim.x + threadIdx.x;
    if (i < N) g_hist[i] = 0;
    if (i < NGRAPH) g_cnt[i] = 0.0f;
}

__global__ void k_hist(const int* __restrict__ ei, int E) {
    int e = blockIdx.x * blockDim.x + threadIdx.x;
    if (e < E) atomicAdd(&g_hist[ei[(size_t)E + e]], 1);
}

__global__ __launch_bounds__(SCAN_B) void k_scan1(int N) {
    __shared__ int wsum[32];
    const int tid = threadIdx.x, lane = tid & 31, wid = tid >> 5;
    int i = blockIdx.x * SCAN_B + tid;
    int v = (i < N) ? g_hist[i] : 0;
    int x = v;
#pragma unroll
    for (int o = 1; o < 32; o <<= 1) {
        int y = __shfl_up_sync(0xffffffffu, x, o);
        if (lane >= o) x += y;
    }
    if (lane == 31) wsum[wid] = x;
    __syncthreads();
    if (wid == 0) {
        int s = wsum[lane];
#pragma unroll
        for (int o = 1; o < 32; o <<= 1) {
            int y = __shfl_up_sync(0xffffffffu, s, o);
            if (lane >= o) s += y;
        }
        wsum[lane] = s;
    }
    __syncthreads();
    int incl = x + (wid > 0 ? wsum[wid - 1] : 0);
    if (i < N) g_rowptr[i + 1] = incl;
    if (tid == SCAN_B - 1) g_bsum[blockIdx.x] = incl;
}

__global__ void k_scan2(int nb) {
    int lane = threadIdx.x;
    int carry = 0;
    for (int base = 0; base < nb; base += 32) {
        int v = (base + lane < nb) ? g_bsum[base + lane] : 0;
        int x = v;
#pragma unroll
        for (int o = 1; o < 32; o <<= 1) {
            int y = __shfl_up_sync(0xffffffffu, x, o);
            if (lane >= o) x += y;
        }
        if (base + lane < nb) g_bsum[base + lane] = x - v + carry;
        carry += __shfl_sync(0xffffffffu, x, 31);
    }
}

__global__ __launch_bounds__(SCAN_B) void k_scan3(const int* __restrict__ batch, int N) {
    int i = blockIdx.x * SCAN_B + threadIdx.x;
    if (i >= N) return;
    int rp = g_rowptr[i + 1] + g_bsum[blockIdx.x];
    g_rowptr[i + 1] = rp;
    int h = g_hist[i];
    g_cursor[i] = rp - h;
    g_dinv[i] = rsqrtf((float)h + 1.0f);
    atomicAdd(&g_cnt[batch[i]], 1.0f);
    if (i == 0) g_rowptr[0] = 0;
}

__global__ void k_fill(const int* __restrict__ ei, int E) {
    int e = blockIdx.x * blockDim.x + threadIdx.x;
    if (e < E) {
        int src = ei[e];
        int dst = ei[(size_t)E + e];
        int pos = atomicAdd(&g_cursor[dst], 1);
        g_csr[pos] = src;
    }
}

// ---------------- weight split: W -> big (tf32 bits) + small (residual) ----------------
__global__ void k_wsplit(const float* __restrict__ W, float* __restrict__ Wb,
                         float* __restrict__ Ws) {
    int i = blockIdx.x * blockDim.x + threadIdx.x;
    if (i < HD * HD) {
        float w = W[i];
        float b = __uint_as_float(__float_as_uint(w) & 0xFFFFE000u);
        Wb[i] = b;
        Ws[i] = w - b;
    }
}

// ---------------- 3xTF32 tensor GEMM (N x 128) @ (128 x 128), epilogue *dinv ----------------
__device__ __forceinline__ void mma8(float* d, const uint32_t* a, const uint32_t* b) {
    asm volatile(
        "mma.sync.aligned.m16n8k8.row.col.f32.tf32.tf32.f32 "
        "{%0,%1,%2,%3}, {%4,%5,%6,%7}, {%8,%9}, {%0,%1,%2,%3};"
        : "+f"(d[0]), "+f"(d[1]), "+f"(d[2]), "+f"(d[3])
        : "r"(a[0]), "r"(a[1]), "r"(a[2]), "r"(a[3]), "r"(b[0]), "r"(b[1]));
}

__global__ __launch_bounds__(256) void k_gemm_tf32(
    const float* __restrict__ A, const float* __restrict__ Wb,
    const float* __restrict__ Ws, int N)
{
    extern __shared__ float sm[];
    float* Asb = sm;                           // [128][ASTRIDE]  A big,  [m][k]
    float* Ass = Asb + 128 * ASTRIDE;          // A small
    float* Wsb = Ass + 128 * ASTRIDE;          // [32][WSTRIDE]   W big,  [k][n]
    float* Wss = Wsb + 32 * WSTRIDE;           // W small

    const int tid  = threadIdx.x;
    const int lane = tid & 31, wid = tid >> 5;
    const int wm = (wid & 3) * 32;             // warp row offset in tile
    const int wn = (wid >> 2) * 64;            // warp col offset
    const int row0 = blockIdx.x * 128;

    float c[2][8][4];
#pragma unroll
    for (int mt = 0; mt < 2; mt++)
#pragma unroll
        for (int nt = 0; nt < 8; nt++)
#pragma unroll
            for (int q = 0; q < 4; q++) c[mt][nt][q] = 0.0f;

    // A staging: each thread owns 16 consecutive k of one row (2 threads/row)
    const int ar = tid >> 1, ah = (tid & 1) * 16;
    float4 pa[4];

    auto ldgA = [&](int ch) {
        if (row0 + ar < N) {
            const float4* src = (const float4*)(A + (size_t)(row0 + ar) * 128 + ch * 32 + ah);
#pragma unroll
            for (int j = 0; j < 4; j++) pa[j] = src[j];
        } else {
#pragma unroll
            for (int j = 0; j < 4; j++) pa[j] = make_float4(0.f, 0.f, 0.f, 0.f);
        }
    };
    auto stsA = [&]() {
        float* db = Asb + ar * ASTRIDE + ah;
        float* ds = Ass + ar * ASTRIDE + ah;
#pragma unroll
        for (int j = 0; j < 4; j++) {
            float4 v = pa[j];
            float4 b, s;
            b.x = __uint_as_float(__float_as_uint(v.x) & 0xFFFFE000u); s.x = v.x - b.x;
            b.y = __uint_as_float(__float_as_uint(v.y) & 0xFFFFE000u); s.y = v.y - b.y;
            b.z = __uint_as_float(__float_as_uint(v.z) & 0xFFFFE000u); s.z = v.z - b.z;
            b.w = __uint_as_float(__float_as_uint(v.w) & 0xFFFFE000u); s.w = v.w - b.w;
            *(float4*)(db + j * 4) = b;
            *(float4*)(ds + j * 4) = s;
        }
    };
    auto ldW = [&](int ch) {
#pragma unroll
        for (int i = 0; i < 4; i++) {
            int idx = tid + i * 256;            // 1024 16B-chunks: 32 rows x 32 chunks
            int r = idx >> 5, q = idx & 31;
            const float* s1 = Wb + (size_t)(ch * 32 + r) * 128 + q * 4;
            const float* s2 = Ws + (size_t)(ch * 32 + r) * 128 + q * 4;
            uint32_t d1 = smem_u32(Wsb + r * WSTRIDE + q * 4);
            uint32_t d2 = smem_u32(Wss + r * WSTRIDE + q * 4);
            asm volatile("cp.async.cg.shared.global [%0], [%1], 16;\n" :: "r"(d1), "l"(s1));
            asm volatile("cp.async.cg.shared.global [%0], [%1], 16;\n" :: "r"(d2), "l"(s2));
        }
    };

    const int gp = lane >> 2;      // groupID
    const int tg = lane & 3;       // threadID_in_group

    ldgA(0);
    for (int ch = 0; ch < 4; ch++) {
        if (ch > 0) __syncthreads();           // previous compute done before overwrite
        stsA();
        ldW(ch);
        asm volatile("cp.async.commit_group;\n");
        asm volatile("cp.async.wait_group 0;\n");
        __syncthreads();
        if (ch < 3) ldgA(ch + 1);

#pragma unroll
        for (int ks = 0; ks < 4; ks++) {
            const int kk = ks * 8;
            uint32_t ab[2][4], as_[2][4];
#pragma unroll
            for (int mt = 0; mt < 2; mt++) {
                int m = wm + mt * 16 + gp;
                int k = kk + tg;
                ab[mt][0] = __float_as_uint(Asb[m * ASTRIDE + k]);
                ab[mt][1] = __float_as_uint(Asb[(m + 8) * ASTRIDE + k]);
                ab[mt][2] = __float_as_uint(Asb[m * ASTRIDE + k + 4]);
                ab[mt][3] = __float_as_uint(Asb[(m + 8) * ASTRIDE + k + 4]);
                as_[mt][0] = __float_as_uint(Ass[m * ASTRIDE + k]);
                as_[mt][1] = __float_as_uint(Ass[(m + 8) * ASTRIDE + k]);
                as_[mt][2] = __float_as_uint(Ass[m * ASTRIDE + k + 4]);
                as_[mt][3] = __float_as_uint(Ass[(m + 8) * ASTRIDE + k + 4]);
            }
            uint32_t bb[8][2], bs[8][2];
#pragma unroll
            for (int nt = 0; nt < 8; nt++) {
                int n = wn + nt * 8 + gp;
                int k = kk + tg;
                bb[nt][0] = __float_as_uint(Wsb[k * WSTRIDE + n]);
                bb[nt][1] = __float_as_uint(Wsb[(k + 4) * WSTRIDE + n]);
                bs[nt][0] = __float_as_uint(Wss[k * WSTRIDE + n]);
                bs[nt][1] = __float_as_uint(Wss[(k + 4) * WSTRIDE + n]);
            }
#pragma unroll
            for (int mt = 0; mt < 2; mt++)
#pragma unroll
                for (int nt = 0; nt < 8; nt++) {
                    mma8(c[mt][nt], ab[mt], bb[nt]);   // big*big
                    mma8(c[mt][nt], ab[mt], bs[nt]);   // big*small
                    mma8(c[mt][nt], as_[mt], bb[nt]);  // small*big
                }
        }
    }

    // epilogue: *dinv[row] -> g_ts
    float* ts = (float*)g_ts;
#pragma unroll
    for (int mt = 0; mt < 2; mt++) {
        int r0 = row0 + wm + mt * 16 + gp;
        int r1 = r0 + 8;
        float s0 = (r0 < N) ? g_dinv[r0] : 0.0f;
        float s1 = (r1 < N) ? g_dinv[r1] : 0.0f;
#pragma unroll
        for (int nt = 0; nt < 8; nt++) {
            int col = wn + nt * 8 + 2 * tg;
            if (r0 < N) {
                float2 v = make_float2(c[mt][nt][0] * s0, c[mt][nt][1] * s0);
                *(float2*)&ts[(size_t)r0 * 128 + col] = v;
            }
            if (r1 < N) {
                float2 v = make_float2(c[mt][nt][2] * s1, c[mt][nt][3] * s1);
                *(float2*)&ts[(size_t)r1 * 128 + col] = v;
            }
        }
    }
}

// ---------------- gather-aggregate + fused finalize (and optional fused pool) ----------------
template <bool POOL>
__global__ __launch_bounds__(256) void k_gather(const float* __restrict__ bias,
                                                const int* __restrict__ batch,
                                                float* __restrict__ out, int N)
{
    int idx  = blockIdx.x * blockDim.x + threadIdx.x;
    int node = idx >> 5, lane = idx & 31;
    if (node >= N) return;

    float4 acc = g_ts[(size_t)node * 32 + lane];   // self loop

    int p   = g_rowptr[node];
    int end = g_rowptr[node + 1];

    for (; p + 4 <= end; p += 4) {
        int s0 = g_csr[p], s1 = g_csr[p + 1], s2 = g_csr[p + 2], s3 = g_csr[p + 3];
        float4 v0 = g_ts[(size_t)s0 * 32 + lane];
        float4 v1 = g_ts[(size_t)s1 * 32 + lane];
        float4 v2 = g_ts[(size_t)s2 * 32 + lane];
        float4 v3 = g_ts[(size_t)s3 * 32 + lane];
        acc.x += v0.x + v1.x + v2.x + v3.x;
        acc.y += v0.y + v1.y + v2.y + v3.y;
        acc.z += v0.z + v1.z + v2.z + v3.z;
        acc.w += v0.w + v1.w + v2.w + v3.w;
    }
    for (; p < end; p++) {
        int s = g_csr[p];
        float4 v = g_ts[(size_t)s * 32 + lane];
        acc.x += v.x; acc.y += v.y; acc.z += v.z; acc.w += v.w;
    }

    float s = g_dinv[node];
    float4 b = *((const float4*)bias + lane);
    float4 o;
    o.x = fmaxf(fmaf(s, acc.x, b.x), 0.f);
    o.y = fmaxf(fmaf(s, acc.y, b.y), 0.f);
    o.z = fmaxf(fmaf(s, acc.z, b.z), 0.f);
    o.w = fmaxf(fmaf(s, acc.w, b.w), 0.f);

    if (POOL) {
        int g = batch[node];
        float* d = out + (size_t)g * 128 + lane * 4;
        asm volatile("red.global.add.v4.f32 [%0], {%1, %2, %3, %4};"
                     :: "l"(d), "f"(o.x), "f"(o.y), "f"(o.z), "f"(o.w) : "memory");
    } else {
        g_h[(size_t)node * 32 + lane] = o;
    }
}

// ---------------- pooling tail ----------------
__global__ void k_zero_out(float* out, int n) {
    int i = blockIdx.x * blockDim.x + threadIdx.x;
    if (i < n) out[i] = 0.0f;
}

__global__ void k_pool_fin(float* out, int n) {
    int i = blockIdx.x * blockDim.x + threadIdx.x;
    if (i < n) {
        int g = i >> 7;
        out[i] = out[i] / fmaxf(g_cnt[g], 1.0f);
    }
}

// ---------------- launch ----------------
extern "C" void kernel_launch(void* const* d_in, const int* in_sizes, int n_in,
                              void* d_out, int out_size) {
    const float* x     = (const float*)d_in[0];
    const float* W1    = (const float*)d_in[2];
    const float* b1    = (const float*)d_in[3];
    const float* W2    = (const float*)d_in[4];
    const float* b2    = (const float*)d_in[5];
    const float* W3    = (const float*)d_in[6];
    const float* b3    = (const float*)d_in[7];
    const int*   ei    = (const int*)d_in[8];
    const int*   batch = (const int*)d_in[9];
    float* out = (float*)d_out;

    const int N = in_sizes[0] / HD;
    const int E = in_sizes[8] / 2;

    void* p_h = nullptr;  cudaGetSymbolAddress(&p_h, g_h);
    void* p_wb = nullptr; cudaGetSymbolAddress(&p_wb, g_Wb);
    void* p_ws = nullptr; cudaGetSymbolAddress(&p_ws, g_Ws);
    const float* hbuf = (const float*)p_h;
    float* wb = (float*)p_wb;
    float* ws = (float*)p_ws;

    const int GEMM_SMEM = (128 * ASTRIDE * 2 + 32 * WSTRIDE * 2) * 4;  // 70656 B
    cudaFuncSetAttribute(k_gemm_tf32, cudaFuncAttributeMaxDynamicSharedMemorySize, GEMM_SMEM);

    const int T = 256;
    const int nb_N = (N + T - 1) / T;
    const int nb_E = (E + T - 1) / T;
    const int gemm_blocks = (N + 127) / 128;
    const int node_warp_blocks = (N * 32 + T - 1) / T;
    const int scan_blocks = (N + SCAN_B - 1) / SCAN_B;

    // CSR build + normalization + weight split
    k_zero_meta<<<nb_N, T>>>(N);
    k_hist<<<nb_E, T>>>(ei, E);
    k_wsplit<<<(HD * HD + T - 1) / T, T>>>(W1, wb + 0 * HD * HD, ws + 0 * HD * HD);
    k_wsplit<<<(HD * HD + T - 1) / T, T>>>(W2, wb + 1 * HD * HD, ws + 1 * HD * HD);
    k_wsplit<<<(HD * HD + T - 1) / T, T>>>(W3, wb + 2 * HD * HD, ws + 2 * HD * HD);
    k_scan1<<<scan_blocks, SCAN_B>>>(N);
    k_scan2<<<1, 32>>>(scan_blocks);
    k_scan3<<<scan_blocks, SCAN_B>>>(batch, N);
    k_fill<<<nb_E, T>>>(ei, E);
    k_zero_out<<<(out_size + T - 1) / T, T>>>(out, out_size);

    // layer 1
    k_gemm_tf32<<<gemm_blocks, T, GEMM_SMEM>>>(x, wb + 0 * HD * HD, ws + 0 * HD * HD, N);
    k_gather<false><<<node_warp_blocks, T>>>(b1, batch, out, N);
    // layer 2
    k_gemm_tf32<<<gemm_blocks, T, GEMM_SMEM>>>(hbuf, wb + 1 * HD * HD, ws + 1 * HD * HD, N);
    k_gather<false><<<node_warp_blocks, T>>>(b2, batch, out, N);
    // layer 3 (fused mean-pool accumulation)
    k_gemm_tf32<<<gemm_blocks, T, GEMM_SMEM>>>(hbuf, wb + 2 * HD * HD, ws + 2 * HD * HD, N);
    k_gather<true><<<node_warp_blocks, T>>>(b3, batch, out, N);

    k_pool_fin<<<(out_size + T - 1) / T, T>>>(out, out_size);
}

// round 8
// speedup vs baseline: 2.3764x; 1.2051x over previous
#include <cuda_runtime.h>
#include <cuda_bf16.h>
#include <stdint.h>

#define NMAX 50000
#define EMAX 1000000
#define HD 128
#define NGRAPH 512
#define SCAN_B 1024
#define MAXBLK 64
#define ASTR 36
#define WSTR 132

// ---------------- scratch (static device globals; no allocation) ----------------
__device__ float  g_dinv[NMAX];
__device__ int    g_hist[NMAX];
__device__ int    g_rowptr[NMAX + 1];
__device__ int    g_cursor[NMAX];
__device__ int    g_bsum[MAXBLK];
__device__ int    g_csr[EMAX];
__device__ float4 g_ts[(size_t)NMAX * HD / 4];   // (h @ W) * dinv[row]
__device__ float4 g_h[(size_t)NMAX * HD / 4];    // layer output
__device__ float  g_cnt[NGRAPH];

__device__ __forceinline__ uint32_t smem_u32(const void* p) {
    return (uint32_t)__cvta_generic_to_shared(p);
}

// ---------------- CSR build ----------------
__global__ void k_zero_meta(int N) {
    int i = blockIdx.x * blockDim.x + threadIdx.x;
    if (i < N) g_hist[i] = 0;
    if (i < NGRAPH) g_cnt[i] = 0.0f;
}

__global__ void k_hist(const int* __restrict__ ei, int E) {
    int e = blockIdx.x * blockDim.x + threadIdx.x;
    if (e < E) atomicAdd(&g_hist[ei[(size_t)E + e]], 1);
}

__global__ __launch_bounds__(SCAN_B) void k_scan1(int N) {
    __shared__ int wsum[32];
    const int tid = threadIdx.x, lane = tid & 31, wid = tid >> 5;
    int i = blockIdx.x * SCAN_B + tid;
    int v = (i < N) ? g_hist[i] : 0;
    int x = v;
#pragma unroll
    for (int o = 1; o < 32; o <<= 1) {
        int y = __shfl_up_sync(0xffffffffu, x, o);
        if (lane >= o) x += y;
    }
    if (lane == 31) wsum[wid] = x;
    __syncthreads();
    if (wid == 0) {
        int s = wsum[lane];
#pragma unroll
        for (int o = 1; o < 32; o <<= 1) {
            int y = __shfl_up_sync(0xffffffffu, s, o);
            if (lane >= o) s += y;
        }
        wsum[lane] = s;
    }
    __syncthreads();
    int incl = x + (wid > 0 ? wsum[wid - 1] : 0);
    if (i < N) g_rowptr[i + 1] = incl;
    if (tid == SCAN_B - 1) g_bsum[blockIdx.x] = incl;
}

__global__ void k_scan2(int nb) {
    int lane = threadIdx.x;
    int carry = 0;
    for (int base = 0; base < nb; base += 32) {
        int v = (base + lane < nb) ? g_bsum[base + lane] : 0;
        int x = v;
#pragma unroll
        for (int o = 1; o < 32; o <<= 1) {
            int y = __shfl_up_sync(0xffffffffu, x, o);
            if (lane >= o) x += y;
        }
        if (base + lane < nb) g_bsum[base + lane] = x - v + carry;
        carry += __shfl_sync(0xffffffffu, x, 31);
    }
}

__global__ __launch_bounds__(SCAN_B) void k_scan3(const int* __restrict__ batch, int N) {
    int i = blockIdx.x * SCAN_B + threadIdx.x;
    if (i >= N) return;
    int rp = g_rowptr[i + 1] + g_bsum[blockIdx.x];
    g_rowptr[i + 1] = rp;
    int h = g_hist[i];
    g_cursor[i] = rp - h;
    g_dinv[i] = rsqrtf((float)h + 1.0f);
    atomicAdd(&g_cnt[batch[i]], 1.0f);
    if (i == 0) g_rowptr[0] = 0;
}

__global__ void k_fill(const int* __restrict__ ei, int E) {
    int e = blockIdx.x * blockDim.x + threadIdx.x;
    if (e < E) {
        int src = ei[e];
        int dst = ei[(size_t)E + e];
        int pos = atomicAdd(&g_cursor[dst], 1);
        g_csr[pos] = src;
    }
}

// ---------------- 3xTF32 tensor GEMM, register-split, 2-stage cp.async pipeline ----------------
__device__ __forceinline__ void mma8(float* d, const uint32_t* a, const uint32_t* b) {
    asm volatile(
        "mma.sync.aligned.m16n8k8.row.col.f32.tf32.tf32.f32 "
        "{%0,%1,%2,%3}, {%4,%5,%6,%7}, {%8,%9}, {%0,%1,%2,%3};"
        : "+f"(d[0]), "+f"(d[1]), "+f"(d[2]), "+f"(d[3])
        : "r"(a[0]), "r"(a[1]), "r"(a[2]), "r"(a[3]), "r"(b[0]), "r"(b[1]));
}

__device__ __forceinline__ float tf32_big(float x) {
    return __uint_as_float(__float_as_uint(x) & 0xFFFFE000u);
}

__global__ __launch_bounds__(256, 2) void k_gemm_tf32(
    const float* __restrict__ A, const float* __restrict__ W, int N)
{
    extern __shared__ float sm[];
    float* As_ = sm;                     // [2][128][ASTR] raw A, [m][k]
    float* Ws_ = As_ + 2 * 128 * ASTR;   // [2][32][WSTR]  raw W, [k][n]

    const int tid  = threadIdx.x;
    const int lane = tid & 31, wid = tid >> 5;
    const int wm = (wid & 3) * 32;       // warp row offset
    const int wn = (wid >> 2) * 64;      // warp col offset
    const int row0 = blockIdx.x * 128;
    const int gp = lane >> 2, tg = lane & 3;

    float c[2][8][4];
#pragma unroll
    for (int mt = 0; mt < 2; mt++)
#pragma unroll
        for (int nt = 0; nt < 8; nt++)
#pragma unroll
            for (int q = 0; q < 4; q++) c[mt][nt][q] = 0.0f;

    auto issueAW = [&](int ch, int buf) {
        // A chunk: 128 rows x 32 k = 1024 16B pieces (zero-fill OOB rows)
#pragma unroll
        for (int i = 0; i < 4; i++) {
            int idx = tid + i * 256;
            int r = idx >> 3, q = idx & 7;
            const float* src = A + (size_t)(row0 + r) * 128 + ch * 32 + q * 4;
            uint32_t dst = smem_u32(As_ + buf * 128 * ASTR + r * ASTR + q * 4);
            int sz = (row0 + r < N) ? 16 : 0;
            asm volatile("cp.async.cg.shared.global [%0], [%1], 16, %2;\n"
                         :: "r"(dst), "l"(src), "r"(sz));
        }
        // W chunk: 32 k-rows x 128 n = 1024 16B pieces
#pragma unroll
        for (int i = 0; i < 4; i++) {
            int idx = tid + i * 256;
            int r = idx >> 5, q = idx & 31;
            const float* src = W + (size_t)(ch * 32 + r) * 128 + q * 4;
            uint32_t dst = smem_u32(Ws_ + buf * 32 * WSTR + r * WSTR + q * 4);
            asm volatile("cp.async.cg.shared.global [%0], [%1], 16;\n"
                         :: "r"(dst), "l"(src));
        }
    };

    issueAW(0, 0);
    asm volatile("cp.async.commit_group;\n");
    issueAW(1, 1);
    asm volatile("cp.async.commit_group;\n");

#pragma unroll
    for (int ch = 0; ch < 4; ch++) {
        const int buf = ch & 1;
        if (ch < 3) asm volatile("cp.async.wait_group 1;\n");
        else        asm volatile("cp.async.wait_group 0;\n");
        __syncthreads();

        const float* Ab = As_ + buf * 128 * ASTR;
        const float* Wb = Ws_ + buf * 32 * WSTR;

#pragma unroll
        for (int ks = 0; ks < 4; ks++) {
            const int kk = ks * 8;
            uint32_t ab[2][4], as2[2][4];
#pragma unroll
            for (int mt = 0; mt < 2; mt++) {
                int m = wm + mt * 16 + gp;
                int k = kk + tg;
                float r0 = Ab[m * ASTR + k];
                float r1 = Ab[(m + 8) * ASTR + k];
                float r2 = Ab[m * ASTR + k + 4];
                float r3 = Ab[(m + 8) * ASTR + k + 4];
                float b0 = tf32_big(r0), b1 = tf32_big(r1);
                float b2 = tf32_big(r2), b3 = tf32_big(r3);
                ab[mt][0] = __float_as_uint(b0);  as2[mt][0] = __float_as_uint(r0 - b0);
                ab[mt][1] = __float_as_uint(b1);  as2[mt][1] = __float_as_uint(r1 - b1);
                ab[mt][2] = __float_as_uint(b2);  as2[mt][2] = __float_as_uint(r2 - b2);
                ab[mt][3] = __float_as_uint(b3);  as2[mt][3] = __float_as_uint(r3 - b3);
            }
#pragma unroll
            for (int nt = 0; nt < 8; nt++) {
                int n = wn + nt * 8 + gp;
                int k = kk + tg;
                float w0 = Wb[k * WSTR + n];
                float w1 = Wb[(k + 4) * WSTR + n];
                float wb0 = tf32_big(w0), wb1 = tf32_big(w1);
                uint32_t bb[2] = {__float_as_uint(wb0), __float_as_uint(wb1)};
                uint32_t bs[2] = {__float_as_uint(w0 - wb0), __float_as_uint(w1 - wb1)};
                mma8(c[0][nt], ab[0], bb);
                mma8(c[1][nt], ab[1], bb);
                mma8(c[0][nt], ab[0], bs);
                mma8(c[1][nt], ab[1], bs);
                mma8(c[0][nt], as2[0], bb);
                mma8(c[1][nt], as2[1], bb);
            }
        }

        __syncthreads();                // all warps done reading buf
        if (ch < 2) {
            issueAW(ch + 2, buf);
            asm volatile("cp.async.commit_group;\n");
        }
    }

    // epilogue: *dinv[row] -> g_ts
    float* ts = (float*)g_ts;
#pragma unroll
    for (int mt = 0; mt < 2; mt++) {
        int r0 = row0 + wm + mt * 16 + gp;
        int r1 = r0 + 8;
        float s0 = (r0 < N) ? g_dinv[r0] : 0.0f;
        float s1 = (r1 < N) ? g_dinv[r1] : 0.0f;
#pragma unroll
        for (int nt = 0; nt < 8; nt++) {
            int col = wn + nt * 8 + 2 * tg;
            if (r0 < N) {
                float2 v = make_float2(c[mt][nt][0] * s0, c[mt][nt][1] * s0);
                *(float2*)&ts[(size_t)r0 * 128 + col] = v;
            }
            if (r1 < N) {
                float2 v = make_float2(c[mt][nt][2] * s1, c[mt][nt][3] * s1);
                *(float2*)&ts[(size_t)r1 * 128 + col] = v;
            }
        }
    }
}

// ---------------- gather-aggregate + fused finalize (and optional fused pool) ----------------
template <bool POOL>
__global__ __launch_bounds__(256) void k_gather(const float* __restrict__ bias,
                                                const int* __restrict__ batch,
                                                float* __restrict__ out, int N)
{
    int idx  = blockIdx.x * blockDim.x + threadIdx.x;
    int node = idx >> 5, lane = idx & 31;
    if (node >= N) return;

    float4 acc = g_ts[(size_t)node * 32 + lane];   // self loop

    int p   = g_rowptr[node];
    int end = g_rowptr[node + 1];

    for (; p + 4 <= end; p += 4) {
        int s0 = g_csr[p], s1 = g_csr[p + 1], s2 = g_csr[p + 2], s3 = g_csr[p + 3];
        float4 v0 = g_ts[(size_t)s0 * 32 + lane];
        float4 v1 = g_ts[(size_t)s1 * 32 + lane];
        float4 v2 = g_ts[(size_t)s2 * 32 + lane];
        float4 v3 = g_ts[(size_t)s3 * 32 + lane];
        acc.x += v0.x + v1.x + v2.x + v3.x;
        acc.y += v0.y + v1.y + v2.y + v3.y;
        acc.z += v0.z + v1.z + v2.z + v3.z;
        acc.w += v0.w + v1.w + v2.w + v3.w;
    }
    for (; p < end; p++) {
        int s = g_csr[p];
        float4 v = g_ts[(size_t)s * 32 + lane];
        acc.x += v.x; acc.y += v.y; acc.z += v.z; acc.w += v.w;
    }

    float s = g_dinv[node];
    float4 b = *((const float4*)bias + lane);
    float4 o;
    o.x = fmaxf(fmaf(s, acc.x, b.x), 0.f);
    o.y = fmaxf(fmaf(s, acc.y, b.y), 0.f);
    o.z = fmaxf(fmaf(s, acc.z, b.z), 0.f);
    o.w = fmaxf(fmaf(s, acc.w, b.w), 0.f);

    if (POOL) {
        int g = batch[node];
        float* d = out + (size_t)g * 128 + lane * 4;
        asm volatile("red.global.add.v4.f32 [%0], {%1, %2, %3, %4};"
                     :: "l"(d), "f"(o.x), "f"(o.y), "f"(o.z), "f"(o.w) : "memory");
    } else {
        g_h[(size_t)node * 32 + lane] = o;
    }
}

// ---------------- pooling tail ----------------
__global__ void k_zero_out(float* out, int n) {
    int i = blockIdx.x * blockDim.x + threadIdx.x;
    if (i < n) out[i] = 0.0f;
}

__global__ void k_pool_fin(float* out, int n) {
    int i = blockIdx.x * blockDim.x + threadIdx.x;
    if (i < n) {
        int g = i >> 7;
        out[i] = out[i] / fmaxf(g_cnt[g], 1.0f);
    }
}

// ---------------- launch ----------------
extern "C" void kernel_launch(void* const* d_in, const int* in_sizes, int n_in,
                              void* d_out, int out_size) {
    const float* x     = (const float*)d_in[0];
    const float* W1    = (const float*)d_in[2];
    const float* b1    = (const float*)d_in[3];
    const float* W2    = (const float*)d_in[4];
    const float* b2    = (const float*)d_in[5];
    const float* W3    = (const float*)d_in[6];
    const float* b3    = (const float*)d_in[7];
    const int*   ei    = (const int*)d_in[8];
    const int*   batch = (const int*)d_in[9];
    float* out = (float*)d_out;

    const int N = in_sizes[0] / HD;
    const int E = in_sizes[8] / 2;

    void* p_h = nullptr;  cudaGetSymbolAddress(&p_h, g_h);
    const float* hbuf = (const float*)p_h;

    const int GEMM_SMEM = (2 * 128 * ASTR + 2 * 32 * WSTR) * 4;  // 70656 B
    cudaFuncSetAttribute(k_gemm_tf32, cudaFuncAttributeMaxDynamicSharedMemorySize, GEMM_SMEM);

    const int T = 256;
    const int nb_N = (N + T - 1) / T;
    const int nb_E = (E + T - 1) / T;
    const int gemm_blocks = (N + 127) / 128;
    const int node_warp_blocks = (N * 32 + T - 1) / T;
    const int scan_blocks = (N + SCAN_B - 1) / SCAN_B;

    // CSR build + normalization
    k_zero_meta<<<nb_N, T>>>(N);
    k_hist<<<nb_E, T>>>(ei, E);
    k_scan1<<<scan_blocks, SCAN_B>>>(N);
    k_scan2<<<1, 32>>>(scan_blocks);
    k_scan3<<<scan_blocks, SCAN_B>>>(batch, N);
    k_fill<<<nb_E, T>>>(ei, E);
    k_zero_out<<<(out_size + T - 1) / T, T>>>(out, out_size);

    // layer 1
    k_gemm_tf32<<<gemm_blocks, T, GEMM_SMEM>>>(x, W1, N);
    k_gather<false><<<node_warp_blocks, T>>>(b1, batch, out, N);
    // layer 2
    k_gemm_tf32<<<gemm_blocks, T, GEMM_SMEM>>>(hbuf, W2, N);
    k_gather<false><<<node_warp_blocks, T>>>(b2, batch, out, N);
    // layer 3 (fused mean-pool accumulation)
    k_gemm_tf32<<<gemm_blocks, T, GEMM_SMEM>>>(hbuf, W3, N);
    k_gather<true><<<node_warp_blocks, T>>>(b3, batch, out, N);

    k_pool_fin<<<(out_size + T - 1) / T, T>>>(out, out_size);
}